// round 1
// baseline (speedup 1.0000x reference)
#include <cuda_runtime.h>
#include <math.h>

#define NB 4
#define NC 512
#define NT 1024
#define NHEADS 8
#define NHD 64
#define EPS_IN 1e-5f

// ---------------- device scratch (no allocations allowed) ----------------
__device__ float g_q[NB * NC * NT];                       // [b][o][t]  8MB
__device__ float g_k[NB * NC * NT];                       // 8MB
__device__ float g_v[NB * NC * NT];                       // 8MB
__device__ float g_attn[(size_t)NB * NHEADS * NT * NT];   // [b][h][q][T] 134MB
__device__ float g_out[NB * NHEADS * NT * NHD];           // [b][h][q][d] == [b][t][c] 8MB
__device__ float g_vsum[NB * NC];                         // sum over T of v
__device__ float g_partial[32 * 16 * 2];                  // stats partials (sum, sumsq)
__device__ float g_alpha[32];
__device__ float g_betac[32];

// ---------------- Kernel 1: QKV (1x1 convs = channel GEMMs) ----------------
// out[b, o, t] = sum_c W[o,c] * x[b,c,t]   M=512(o), N=1024(t), K=512
__global__ void qkv_kernel(const float* __restrict__ x,
                           const float* __restrict__ wq,
                           const float* __restrict__ wk,
                           const float* __restrict__ wv) {
    int z = blockIdx.z;            // b*3 + which
    int b = z / 3, which = z - b * 3;
    const float* W = (which == 0) ? wq : (which == 1) ? wk : wv;
    float* out = ((which == 0) ? g_q : (which == 1) ? g_k : g_v) + b * NC * NT;
    const float* X = x + b * NC * NT;

    int oBase = blockIdx.y * 64;
    int tBase = blockIdx.x * 64;

    __shared__ float As[16][65];   // [c][o]
    __shared__ float Bs[16][65];   // [c][t]

    int tid = threadIdx.x;
    int tx = tid & 15, ty = tid >> 4;
    float acc[4][4];
#pragma unroll
    for (int i = 0; i < 4; i++)
#pragma unroll
        for (int j = 0; j < 4; j++) acc[i][j] = 0.f;

    for (int k0 = 0; k0 < NC; k0 += 16) {
#pragma unroll
        for (int i = 0; i < 4; i++) {
            int idx = tid + i * 256;
            int o = idx >> 4, c = idx & 15;
            As[c][o] = W[(oBase + o) * NC + k0 + c];
        }
#pragma unroll
        for (int i = 0; i < 4; i++) {
            int idx = tid + i * 256;
            int c = idx >> 6, t = idx & 63;
            Bs[c][t] = X[(k0 + c) * NT + tBase + t];
        }
        __syncthreads();
#pragma unroll
        for (int kk = 0; kk < 16; kk++) {
            float a[4], bb[4];
#pragma unroll
            for (int i = 0; i < 4; i++) a[i] = As[kk][ty * 4 + i];
#pragma unroll
            for (int j = 0; j < 4; j++) bb[j] = Bs[kk][tx * 4 + j];
#pragma unroll
            for (int i = 0; i < 4; i++)
#pragma unroll
                for (int j = 0; j < 4; j++) acc[i][j] += a[i] * bb[j];
        }
        __syncthreads();
    }
#pragma unroll
    for (int i = 0; i < 4; i++)
#pragma unroll
        for (int j = 0; j < 4; j++)
            out[(oBase + ty * 4 + i) * NT + tBase + tx * 4 + j] = acc[i][j];
}

// ---------------- Kernel 2: attn_raw = scale * Q^T K per (b,h) ----------------
// attn[q,T] = 0.125 * sum_d q[d,q]*k[d,T]   M=N=1024, K=64
__global__ void qk_kernel() {
    int bh = blockIdx.z;
    int b = bh >> 3, h = bh & 7;
    const float* A = g_q + b * NC * NT + h * NHD * NT;   // [d][q], row stride NT
    const float* Bm = g_k + b * NC * NT + h * NHD * NT;  // [d][T]
    float* out = g_attn + (size_t)bh * NT * NT;

    int qBase = blockIdx.y * 64;
    int tBase = blockIdx.x * 64;

    __shared__ float As[16][65];
    __shared__ float Bs[16][65];

    int tid = threadIdx.x;
    int tx = tid & 15, ty = tid >> 4;
    float acc[4][4];
#pragma unroll
    for (int i = 0; i < 4; i++)
#pragma unroll
        for (int j = 0; j < 4; j++) acc[i][j] = 0.f;

    for (int k0 = 0; k0 < NHD; k0 += 16) {
#pragma unroll
        for (int i = 0; i < 4; i++) {
            int idx = tid + i * 256;
            int d = idx >> 6, m = idx & 63;
            As[d][m] = A[(k0 + d) * NT + qBase + m];
            Bs[d][m] = Bm[(k0 + d) * NT + tBase + m];
        }
        __syncthreads();
#pragma unroll
        for (int kk = 0; kk < 16; kk++) {
            float a[4], bb[4];
#pragma unroll
            for (int i = 0; i < 4; i++) a[i] = As[kk][ty * 4 + i];
#pragma unroll
            for (int j = 0; j < 4; j++) bb[j] = Bs[kk][tx * 4 + j];
#pragma unroll
            for (int i = 0; i < 4; i++)
#pragma unroll
                for (int j = 0; j < 4; j++) acc[i][j] += a[i] * bb[j];
        }
        __syncthreads();
    }
#pragma unroll
    for (int i = 0; i < 4; i++)
#pragma unroll
        for (int j = 0; j < 4; j++)
            out[(size_t)(qBase + ty * 4 + i) * NT + tBase + tx * 4 + j] = acc[i][j] * 0.125f;
}

// ---------------- Kernel 3: fused head-mix + softmax (in place) ----------------
// One block per (b,q). Warp g computes mixed row g, softmaxes it, writes it back.
__global__ void mixsm_kernel(const float* __restrict__ w_head) {
    int q = blockIdx.x, b = blockIdx.y;
    __shared__ float raw[8][NT];

    for (int idx = threadIdx.x; idx < 8 * NT; idx += 256) {
        int h = idx >> 10, Tt = idx & 1023;
        raw[h][Tt] = g_attn[(((size_t)(b * 8 + h)) * NT + q) * NT + Tt];
    }
    __syncthreads();

    int g = threadIdx.x >> 5, lane = threadIdx.x & 31;
    float wh[8];
#pragma unroll
    for (int h = 0; h < 8; h++) wh[h] = w_head[g * 8 + h];

    float vals[32];
    float mx = -1e30f;
#pragma unroll
    for (int i = 0; i < 32; i++) {
        int Tt = i * 32 + lane;
        float m = 0.f;
#pragma unroll
        for (int h = 0; h < 8; h++) m += wh[h] * raw[h][Tt];
        vals[i] = m;
        mx = fmaxf(mx, m);
    }
#pragma unroll
    for (int off = 16; off > 0; off >>= 1)
        mx = fmaxf(mx, __shfl_xor_sync(0xffffffffu, mx, off));

    float s = 0.f;
#pragma unroll
    for (int i = 0; i < 32; i++) {
        vals[i] = __expf(vals[i] - mx);
        s += vals[i];
    }
#pragma unroll
    for (int off = 16; off > 0; off >>= 1)
        s += __shfl_xor_sync(0xffffffffu, s, off);

    float inv = 1.f / s;
    size_t base = (((size_t)(b * 8 + g)) * NT + q) * NT;
#pragma unroll
    for (int i = 0; i < 32; i++)
        g_attn[base + i * 32 + lane] = vals[i] * inv;
}

// ---------------- Kernel 4: vsum[row] = sum_T v[row][T] ----------------
__global__ void vsum_kernel() {
    __shared__ float sbuf[8];
    int row = blockIdx.x;
    const float* p = g_v + (size_t)row * NT;
    float s = 0.f;
    for (int i = threadIdx.x; i < NT; i += 256) s += p[i];
    int lane = threadIdx.x & 31, w = threadIdx.x >> 5;
#pragma unroll
    for (int o = 16; o > 0; o >>= 1) s += __shfl_xor_sync(0xffffffffu, s, o);
    if (lane == 0) sbuf[w] = s;
    __syncthreads();
    if (threadIdx.x == 0) {
        float t = 0.f;
        for (int i = 0; i < 8; i++) t += sbuf[i];
        g_vsum[row] = t;
    }
}

// ---------------- Kernel 5: InstanceNorm stats (two-stage, deterministic) ----------------
__global__ void stats_kernel() {
    __shared__ float sbuf[16];
    int grp = blockIdx.y;      // 0..31 (b*8+g)
    int chunk = blockIdx.x;    // 0..15
    size_t base = (size_t)grp * NT * NT + (size_t)chunk * 65536;
    float s = 0.f, sq = 0.f;
    for (int i = threadIdx.x; i < 65536; i += 256) {
        float a = g_attn[base + i];
        s += a;
        sq += a * a;
    }
    int lane = threadIdx.x & 31, w = threadIdx.x >> 5;
#pragma unroll
    for (int o = 16; o > 0; o >>= 1) s += __shfl_xor_sync(0xffffffffu, s, o);
    if (lane == 0) sbuf[w] = s;
    __syncthreads();
    if (threadIdx.x == 0) {
        float t = 0.f;
        for (int i = 0; i < 8; i++) t += sbuf[i];
        g_partial[(grp * 16 + chunk) * 2] = t;
    }
    __syncthreads();
#pragma unroll
    for (int o = 16; o > 0; o >>= 1) sq += __shfl_xor_sync(0xffffffffu, sq, o);
    if (lane == 0) sbuf[w] = sq;
    __syncthreads();
    if (threadIdx.x == 0) {
        float t = 0.f;
        for (int i = 0; i < 8; i++) t += sbuf[i];
        g_partial[(grp * 16 + chunk) * 2 + 1] = t;
    }
}

__global__ void finalize_kernel(const float* __restrict__ gamma,
                                const float* __restrict__ beta) {
    int grp = threadIdx.x;
    if (grp < 32) {
        float s = 0.f, sq = 0.f;
        for (int i = 0; i < 16; i++) {
            s += g_partial[(grp * 16 + i) * 2];
            sq += g_partial[(grp * 16 + i) * 2 + 1];
        }
        const float invN = 1.f / (1024.f * 1024.f);
        float mean = s * invN;
        float var = sq * invN - mean * mean;
        int h = grp & 7;
        float alpha = gamma[h] * rsqrtf(var + EPS_IN);
        g_alpha[grp] = alpha;
        g_betac[grp] = beta[h] - alpha * mean;
    }
}

// ---------------- Kernel 6: AV with folded InstanceNorm ----------------
// out[q,d] = alpha * sum_T attn[q,T]*v[d,T] + betac * vsum[d]
// M=1024(q), N=64(d), K=1024 per (b,h)
__global__ void av_kernel() {
    int bh = blockIdx.y;
    int b = bh >> 3, h = bh & 7;
    const float* A = g_attn + (size_t)bh * NT * NT;             // [q][T]
    const float* V = g_v + b * NC * NT + h * NHD * NT;          // [d][T], stride NT
    float* out = g_out + (size_t)bh * NT * NHD;                 // [q][d]
    int qBase = blockIdx.x * 64;

    __shared__ float As[16][65];   // [kT][q]
    __shared__ float Bs[16][65];   // [kT][d]

    int tid = threadIdx.x;
    int tx = tid & 15, ty = tid >> 4;
    float acc[4][4];
#pragma unroll
    for (int i = 0; i < 4; i++)
#pragma unroll
        for (int j = 0; j < 4; j++) acc[i][j] = 0.f;

    for (int k0 = 0; k0 < NT; k0 += 16) {
#pragma unroll
        for (int i = 0; i < 4; i++) {
            int idx = tid + i * 256;
            int m = idx >> 4, kT = idx & 15;
            As[kT][m] = A[(size_t)(qBase + m) * NT + k0 + kT];
            Bs[kT][m] = V[(size_t)m * NT + k0 + kT];
        }
        __syncthreads();
#pragma unroll
        for (int kk = 0; kk < 16; kk++) {
            float a[4], bb[4];
#pragma unroll
            for (int i = 0; i < 4; i++) a[i] = As[kk][ty * 4 + i];
#pragma unroll
            for (int j = 0; j < 4; j++) bb[j] = Bs[kk][tx * 4 + j];
#pragma unroll
            for (int i = 0; i < 4; i++)
#pragma unroll
                for (int j = 0; j < 4; j++) acc[i][j] += a[i] * bb[j];
        }
        __syncthreads();
    }
    float alpha = g_alpha[bh], bc = g_betac[bh];
#pragma unroll
    for (int i = 0; i < 4; i++)
#pragma unroll
        for (int j = 0; j < 4; j++) {
            int d = tx * 4 + j;
            out[(qBase + ty * 4 + i) * NHD + d] =
                alpha * acc[i][j] + bc * g_vsum[bh * NHD + d];
        }
}

// ---------------- Kernel 7: output projection + bias + transpose ----------------
// mid[b,t,c] is g_out reinterpreted (contiguous reshape).
// final[b, co, t] = sum_c mid[b,t,c]*w_proj[co,c] + b_proj[co]
// M=512(co, ty), N=1024(t, tx), K=512
__global__ void proj_kernel(const float* __restrict__ w_proj,
                            const float* __restrict__ b_proj,
                            float* __restrict__ outF) {
    int b = blockIdx.z;
    int coBase = blockIdx.y * 64;
    int tBase = blockIdx.x * 64;
    const float* mid = g_out + b * NT * NC;   // [t][c]

    __shared__ float As[16][65];   // [c][co]
    __shared__ float Bs[16][65];   // [c][t]

    int tid = threadIdx.x;
    int tx = tid & 15, ty = tid >> 4;
    float acc[4][4];
#pragma unroll
    for (int i = 0; i < 4; i++)
#pragma unroll
        for (int j = 0; j < 4; j++) acc[i][j] = 0.f;

    for (int k0 = 0; k0 < NC; k0 += 16) {
#pragma unroll
        for (int i = 0; i < 4; i++) {
            int idx = tid + i * 256;
            int r = idx >> 4, c = idx & 15;
            As[c][r] = w_proj[(coBase + r) * NC + k0 + c];
            Bs[c][r] = mid[(tBase + r) * NC + k0 + c];
        }
        __syncthreads();
#pragma unroll
        for (int kk = 0; kk < 16; kk++) {
            float a[4], bb[4];
#pragma unroll
            for (int i = 0; i < 4; i++) a[i] = As[kk][ty * 4 + i];
#pragma unroll
            for (int j = 0; j < 4; j++) bb[j] = Bs[kk][tx * 4 + j];
#pragma unroll
            for (int i = 0; i < 4; i++)
#pragma unroll
                for (int j = 0; j < 4; j++) acc[i][j] += a[i] * bb[j];
        }
        __syncthreads();
    }
#pragma unroll
    for (int i = 0; i < 4; i++) {
        int co = coBase + ty * 4 + i;
        float bias = b_proj[co];
#pragma unroll
        for (int j = 0; j < 4; j++)
            outF[b * NC * NT + co * NT + tBase + tx * 4 + j] = acc[i][j] + bias;
    }
}

// ---------------- launch ----------------
extern "C" void kernel_launch(void* const* d_in, const int* in_sizes, int n_in,
                              void* d_out, int out_size) {
    (void)in_sizes; (void)n_in; (void)out_size;
    const float* x        = (const float*)d_in[0];
    const float* w_q      = (const float*)d_in[1];
    const float* w_k      = (const float*)d_in[2];
    const float* w_v      = (const float*)d_in[3];
    const float* w_head   = (const float*)d_in[4];
    const float* in_gamma = (const float*)d_in[5];
    const float* in_beta  = (const float*)d_in[6];
    const float* w_proj   = (const float*)d_in[7];
    const float* b_proj   = (const float*)d_in[8];
    float* outF = (float*)d_out;

    qkv_kernel<<<dim3(16, 8, 12), 256>>>(x, w_q, w_k, w_v);
    qk_kernel<<<dim3(16, 16, 32), 256>>>();
    mixsm_kernel<<<dim3(1024, 4), 256>>>(w_head);
    vsum_kernel<<<2048, 256>>>();
    stats_kernel<<<dim3(16, 32), 256>>>();
    finalize_kernel<<<1, 32>>>(in_gamma, in_beta);
    av_kernel<<<dim3(16, 32), 256>>>();
    proj_kernel<<<dim3(16, 8, 4), 256>>>(w_proj, b_proj, outF);
}

// round 2
// speedup vs baseline: 1.5088x; 1.5088x over previous
#include <cuda_runtime.h>
#include <math.h>

#define NB 4
#define NC 512
#define NT 1024
#define NHEADS 8
#define NHD 64
#define EPS_IN 1e-5f

// ---------------- device scratch ----------------
__device__ float g_q[NB * NC * NT];
__device__ float g_k[NB * NC * NT];
__device__ float g_v[NB * NC * NT];
__device__ float g_attn[(size_t)NB * NHEADS * NT * NT];   // 134MB
__device__ float g_out[NB * NHEADS * NT * NHD];           // == [b][t][c]
__device__ float g_vsum[NB * NC];
__device__ float g_rowsq[NB * NHEADS * NT];
__device__ float g_alpha[32];
__device__ float g_betac[32];

// ============ Kernel 1: QKV 1x1 convs. out[o,t] = sum_c W[o,c] x[c,t] ============
// M=512(o) N=1024(t) K=512. 128x128 tile, BK=8, 8x8 micro (4+4 split).
__global__ __launch_bounds__(256) void qkv_kernel(const float* __restrict__ x,
                                                  const float* __restrict__ wq,
                                                  const float* __restrict__ wk,
                                                  const float* __restrict__ wv) {
    int z = blockIdx.z;
    int b = z / 3, which = z - b * 3;
    const float* W = (which == 0) ? wq : (which == 1) ? wk : wv;
    float* out = ((which == 0) ? g_q : (which == 1) ? g_k : g_v) + (size_t)b * NC * NT;
    const float* X = x + (size_t)b * NC * NT;

    int oBase = blockIdx.y * 128;
    int tBase = blockIdx.x * 128;

    __shared__ float As[8][132];   // [c][o]
    __shared__ float Bs[8][132];   // [c][t]

    int tid = threadIdx.x;
    int tx = tid & 15, ty = tid >> 4;

    float acc[8][8];
#pragma unroll
    for (int i = 0; i < 8; i++)
#pragma unroll
        for (int j = 0; j < 8; j++) acc[i][j] = 0.f;

    int lo = tid >> 1, lch = (tid & 1) * 4;       // W loader: [128 o][8 c]
    int lc = tid >> 5, lt4 = (tid & 31) * 4;      // X loader: [8 c][128 t]
    const float* Wp = W + (size_t)(oBase + lo) * NC + lch;
    const float* Xp = X + (size_t)lc * NT + tBase + lt4;

    for (int k0 = 0; k0 < NC; k0 += 8) {
        float4 w4 = *(const float4*)(Wp + k0);
        float4 x4 = *(const float4*)(Xp + (size_t)k0 * NT);
        As[lch + 0][lo] = w4.x; As[lch + 1][lo] = w4.y;
        As[lch + 2][lo] = w4.z; As[lch + 3][lo] = w4.w;
        *(float4*)&Bs[lc][lt4] = x4;
        __syncthreads();
#pragma unroll
        for (int kk = 0; kk < 8; kk++) {
            float a[8], bb[8];
            *(float4*)a       = *(const float4*)&As[kk][ty * 4];
            *(float4*)(a + 4) = *(const float4*)&As[kk][64 + ty * 4];
            *(float4*)bb       = *(const float4*)&Bs[kk][tx * 4];
            *(float4*)(bb + 4) = *(const float4*)&Bs[kk][64 + tx * 4];
#pragma unroll
            for (int i = 0; i < 8; i++)
#pragma unroll
                for (int j = 0; j < 8; j++) acc[i][j] += a[i] * bb[j];
        }
        __syncthreads();
    }
#pragma unroll
    for (int i = 0; i < 8; i++) {
        int row = oBase + ((i < 4) ? (ty * 4 + i) : (64 + ty * 4 + i - 4));
        float* op = out + (size_t)row * NT + tBase;
        *(float4*)&op[tx * 4]      = make_float4(acc[i][0], acc[i][1], acc[i][2], acc[i][3]);
        *(float4*)&op[64 + tx * 4] = make_float4(acc[i][4], acc[i][5], acc[i][6], acc[i][7]);
    }
}

// ============ Kernel 2: QK^T. attn[q,T] = 0.125 * sum_d q[d,q] k[d,T] ============
// M=N=1024, K=64 per (b,h). 128x128 tile, BK=8.
__global__ __launch_bounds__(256) void qk_kernel() {
    int bh = blockIdx.z;
    int b = bh >> 3, h = bh & 7;
    const float* A  = g_q + (size_t)b * NC * NT + (size_t)h * NHD * NT;  // [d][q]
    const float* Bm = g_k + (size_t)b * NC * NT + (size_t)h * NHD * NT;  // [d][T]
    float* out = g_attn + (size_t)bh * NT * NT;

    int qBase = blockIdx.y * 128;
    int tBase = blockIdx.x * 128;

    __shared__ float As[8][132];
    __shared__ float Bs[8][132];

    int tid = threadIdx.x;
    int tx = tid & 15, ty = tid >> 4;

    float acc[8][8];
#pragma unroll
    for (int i = 0; i < 8; i++)
#pragma unroll
        for (int j = 0; j < 8; j++) acc[i][j] = 0.f;

    int ld = tid >> 5, lm4 = (tid & 31) * 4;   // loader: [8 d][128 m]
    const float* Ap = A  + (size_t)ld * NT + qBase + lm4;
    const float* Bp = Bm + (size_t)ld * NT + tBase + lm4;

    for (int k0 = 0; k0 < NHD; k0 += 8) {
        float4 a4 = *(const float4*)(Ap + (size_t)k0 * NT);
        float4 b4 = *(const float4*)(Bp + (size_t)k0 * NT);
        *(float4*)&As[ld][lm4] = a4;
        *(float4*)&Bs[ld][lm4] = b4;
        __syncthreads();
#pragma unroll
        for (int kk = 0; kk < 8; kk++) {
            float a[8], bb[8];
            *(float4*)a       = *(const float4*)&As[kk][ty * 4];
            *(float4*)(a + 4) = *(const float4*)&As[kk][64 + ty * 4];
            *(float4*)bb       = *(const float4*)&Bs[kk][tx * 4];
            *(float4*)(bb + 4) = *(const float4*)&Bs[kk][64 + tx * 4];
#pragma unroll
            for (int i = 0; i < 8; i++)
#pragma unroll
                for (int j = 0; j < 8; j++) acc[i][j] += a[i] * bb[j];
        }
        __syncthreads();
    }
#pragma unroll
    for (int i = 0; i < 8; i++) {
        int row = qBase + ((i < 4) ? (ty * 4 + i) : (64 + ty * 4 + i - 4));
        float* op = out + (size_t)row * NT + tBase;
        *(float4*)&op[tx * 4] = make_float4(acc[i][0] * 0.125f, acc[i][1] * 0.125f,
                                            acc[i][2] * 0.125f, acc[i][3] * 0.125f);
        *(float4*)&op[64 + tx * 4] = make_float4(acc[i][4] * 0.125f, acc[i][5] * 0.125f,
                                                 acc[i][6] * 0.125f, acc[i][7] * 0.125f);
    }
}

// ============ Kernel 3: head-mix + softmax + row sumsq (in place) ============
__global__ __launch_bounds__(256) void mixsm_kernel(const float* __restrict__ w_head) {
    int q = blockIdx.x, b = blockIdx.y;
    __shared__ float raw[8][NT];

    for (int idx = threadIdx.x; idx < 8 * NT / 4; idx += 256) {
        int h = idx >> 8, t4 = (idx & 255) * 4;
        *(float4*)&raw[h][t4] =
            *(const float4*)&g_attn[(((size_t)(b * 8 + h)) * NT + q) * NT + t4];
    }
    __syncthreads();

    int g = threadIdx.x >> 5, lane = threadIdx.x & 31;
    float wh[8];
#pragma unroll
    for (int h = 0; h < 8; h++) wh[h] = w_head[g * 8 + h];

    float vals[32];
    float mx = -1e30f;
#pragma unroll
    for (int i = 0; i < 32; i++) {
        int Tt = i * 32 + lane;
        float m = 0.f;
#pragma unroll
        for (int h = 0; h < 8; h++) m += wh[h] * raw[h][Tt];
        vals[i] = m;
        mx = fmaxf(mx, m);
    }
#pragma unroll
    for (int off = 16; off > 0; off >>= 1)
        mx = fmaxf(mx, __shfl_xor_sync(0xffffffffu, mx, off));

    float s = 0.f, s2 = 0.f;
#pragma unroll
    for (int i = 0; i < 32; i++) {
        vals[i] = __expf(vals[i] - mx);
        s += vals[i];
        s2 += vals[i] * vals[i];
    }
#pragma unroll
    for (int off = 16; off > 0; off >>= 1) {
        s  += __shfl_xor_sync(0xffffffffu, s, off);
        s2 += __shfl_xor_sync(0xffffffffu, s2, off);
    }

    float inv = 1.f / s;
    size_t base = (((size_t)(b * 8 + g)) * NT + q) * NT;
#pragma unroll
    for (int i = 0; i < 32; i++)
        g_attn[base + i * 32 + lane] = vals[i] * inv;

    if (lane == 0)
        g_rowsq[(b * 8 + g) * NT + q] = s2 * inv * inv;   // sum of p^2 for this row
}

// ============ Kernel 4: vsum[row] = sum_T v[row][T] ============
__global__ __launch_bounds__(256) void vsum_kernel() {
    __shared__ float sbuf[8];
    int row = blockIdx.x;
    float4 p = *(const float4*)&g_v[(size_t)row * NT + threadIdx.x * 4];
    float s = p.x + p.y + p.z + p.w;
    int lane = threadIdx.x & 31, w = threadIdx.x >> 5;
#pragma unroll
    for (int o = 16; o > 0; o >>= 1) s += __shfl_xor_sync(0xffffffffu, s, o);
    if (lane == 0) sbuf[w] = s;
    __syncthreads();
    if (threadIdx.x == 0) {
        float t = 0.f;
        for (int i = 0; i < 8; i++) t += sbuf[i];
        g_vsum[row] = t;
    }
}

// ============ Kernel 5: finalize InstanceNorm params ============
// mean over (T,T) of softmaxed attn = T/T^2 = 1/T exactly (rows sum to 1).
__global__ __launch_bounds__(256) void finalize_kernel(const float* __restrict__ gamma,
                                                       const float* __restrict__ beta) {
    __shared__ float sbuf[8];
    int grp = blockIdx.x;   // b*8+g
    float s = 0.f;
    for (int i = threadIdx.x; i < NT; i += 256) s += g_rowsq[grp * NT + i];
    int lane = threadIdx.x & 31, w = threadIdx.x >> 5;
#pragma unroll
    for (int o = 16; o > 0; o >>= 1) s += __shfl_xor_sync(0xffffffffu, s, o);
    if (lane == 0) sbuf[w] = s;
    __syncthreads();
    if (threadIdx.x == 0) {
        float sumsq = 0.f;
        for (int i = 0; i < 8; i++) sumsq += sbuf[i];
        const float invN = 1.f / (1024.f * 1024.f);
        float mean = 1.f / 1024.f;
        float var = sumsq * invN - mean * mean;
        int h = grp & 7;
        float alpha = gamma[h] * rsqrtf(var + EPS_IN);
        g_alpha[grp] = alpha;
        g_betac[grp] = beta[h] - alpha * mean;
    }
}

// ============ Kernel 6: AV + folded InstanceNorm ============
// out[q,d] = alpha * sum_T attn[q,T] v[d,T] + betac * vsum[d]
// M=1024(q) N=64(d) K=1024. 128x64 tile, BK=16, 8x4 micro.
__global__ __launch_bounds__(256) void av_kernel() {
    int bh = blockIdx.y;
    int b = bh >> 3, h = bh & 7;
    const float* A = g_attn + (size_t)bh * NT * NT;                       // [q][T]
    const float* V = g_v + (size_t)b * NC * NT + (size_t)h * NHD * NT;    // [d][T]
    float* out = g_out + (size_t)bh * NT * NHD;                           // [q][d]
    int qBase = blockIdx.x * 128;

    __shared__ float As[16][132];  // [kT][q]
    __shared__ float Bs[16][68];   // [kT][d]

    int tid = threadIdx.x;
    int tx = tid & 15, ty = tid >> 4;

    float acc[8][4];
#pragma unroll
    for (int i = 0; i < 8; i++)
#pragma unroll
        for (int j = 0; j < 4; j++) acc[i][j] = 0.f;

    int am = tid >> 1, akh = (tid & 1) * 8;   // A loader: [128 q][16 k]
    int bd = tid >> 2, bkq = (tid & 3) * 4;   // V loader: [64 d][16 k]
    const float* Ap = A + (size_t)(qBase + am) * NT + akh;
    const float* Vp = V + (size_t)bd * NT + bkq;

    for (int k0 = 0; k0 < NT; k0 += 16) {
        float4 a0 = *(const float4*)(Ap + k0);
        float4 a1 = *(const float4*)(Ap + k0 + 4);
        As[akh + 0][am] = a0.x; As[akh + 1][am] = a0.y;
        As[akh + 2][am] = a0.z; As[akh + 3][am] = a0.w;
        As[akh + 4][am] = a1.x; As[akh + 5][am] = a1.y;
        As[akh + 6][am] = a1.z; As[akh + 7][am] = a1.w;
        float4 v4 = *(const float4*)(Vp + k0);
        Bs[bkq + 0][bd] = v4.x; Bs[bkq + 1][bd] = v4.y;
        Bs[bkq + 2][bd] = v4.z; Bs[bkq + 3][bd] = v4.w;
        __syncthreads();
#pragma unroll
        for (int kk = 0; kk < 16; kk++) {
            float a[8], bb[4];
            *(float4*)a       = *(const float4*)&As[kk][ty * 4];
            *(float4*)(a + 4) = *(const float4*)&As[kk][64 + ty * 4];
            *(float4*)bb       = *(const float4*)&Bs[kk][tx * 4];
#pragma unroll
            for (int i = 0; i < 8; i++)
#pragma unroll
                for (int j = 0; j < 4; j++) acc[i][j] += a[i] * bb[j];
        }
        __syncthreads();
    }

    float alpha = g_alpha[bh], bc = g_betac[bh];
    float4 vs = *(const float4*)&g_vsum[bh * NHD + tx * 4];
    float vsa[4] = {vs.x, vs.y, vs.z, vs.w};
#pragma unroll
    for (int i = 0; i < 8; i++) {
        int row = qBase + ((i < 4) ? (ty * 4 + i) : (64 + ty * 4 + i - 4));
        float* op = out + (size_t)row * NHD + tx * 4;
        *(float4*)op = make_float4(alpha * acc[i][0] + bc * vsa[0],
                                   alpha * acc[i][1] + bc * vsa[1],
                                   alpha * acc[i][2] + bc * vsa[2],
                                   alpha * acc[i][3] + bc * vsa[3]);
    }
}

// ============ Kernel 7: projection + bias + transpose ============
// final[co, t] = sum_c mid[t,c] w_proj[co,c] + b_proj[co]
// M=512(co) N=1024(t) K=512. 128x128 tile, BK=8.
__global__ __launch_bounds__(256) void proj_kernel(const float* __restrict__ w_proj,
                                                   const float* __restrict__ b_proj,
                                                   float* __restrict__ outF) {
    int b = blockIdx.z;
    int coBase = blockIdx.y * 128;
    int tBase = blockIdx.x * 128;
    const float* mid = g_out + (size_t)b * NT * NC;   // [t][c]

    __shared__ float As[8][132];   // [c][co]
    __shared__ float Bs[8][132];   // [c][t]

    int tid = threadIdx.x;
    int tx = tid & 15, ty = tid >> 4;

    float acc[8][8];
#pragma unroll
    for (int i = 0; i < 8; i++)
#pragma unroll
        for (int j = 0; j < 8; j++) acc[i][j] = 0.f;

    int lr = tid >> 1, lch = (tid & 1) * 4;
    const float* Wp = w_proj + (size_t)(coBase + lr) * NC + lch;
    const float* Mp = mid + (size_t)(tBase + lr) * NC + lch;

    for (int k0 = 0; k0 < NC; k0 += 8) {
        float4 w4 = *(const float4*)(Wp + k0);
        float4 m4 = *(const float4*)(Mp + k0);
        As[lch + 0][lr] = w4.x; As[lch + 1][lr] = w4.y;
        As[lch + 2][lr] = w4.z; As[lch + 3][lr] = w4.w;
        Bs[lch + 0][lr] = m4.x; Bs[lch + 1][lr] = m4.y;
        Bs[lch + 2][lr] = m4.z; Bs[lch + 3][lr] = m4.w;
        __syncthreads();
#pragma unroll
        for (int kk = 0; kk < 8; kk++) {
            float a[8], bb[8];
            *(float4*)a       = *(const float4*)&As[kk][ty * 4];
            *(float4*)(a + 4) = *(const float4*)&As[kk][64 + ty * 4];
            *(float4*)bb       = *(const float4*)&Bs[kk][tx * 4];
            *(float4*)(bb + 4) = *(const float4*)&Bs[kk][64 + tx * 4];
#pragma unroll
            for (int i = 0; i < 8; i++)
#pragma unroll
                for (int j = 0; j < 8; j++) acc[i][j] += a[i] * bb[j];
        }
        __syncthreads();
    }
#pragma unroll
    for (int i = 0; i < 8; i++) {
        int co = coBase + ((i < 4) ? (ty * 4 + i) : (64 + ty * 4 + i - 4));
        float bias = b_proj[co];
        float* op = outF + (size_t)b * NC * NT + (size_t)co * NT + tBase;
        *(float4*)&op[tx * 4] = make_float4(acc[i][0] + bias, acc[i][1] + bias,
                                            acc[i][2] + bias, acc[i][3] + bias);
        *(float4*)&op[64 + tx * 4] = make_float4(acc[i][4] + bias, acc[i][5] + bias,
                                                 acc[i][6] + bias, acc[i][7] + bias);
    }
}

// ---------------- launch ----------------
extern "C" void kernel_launch(void* const* d_in, const int* in_sizes, int n_in,
                              void* d_out, int out_size) {
    (void)in_sizes; (void)n_in; (void)out_size;
    const float* x        = (const float*)d_in[0];
    const float* w_q      = (const float*)d_in[1];
    const float* w_k      = (const float*)d_in[2];
    const float* w_v      = (const float*)d_in[3];
    const float* w_head   = (const float*)d_in[4];
    const float* in_gamma = (const float*)d_in[5];
    const float* in_beta  = (const float*)d_in[6];
    const float* w_proj   = (const float*)d_in[7];
    const float* b_proj   = (const float*)d_in[8];
    float* outF = (float*)d_out;

    qkv_kernel<<<dim3(8, 4, 12), 256>>>(x, w_q, w_k, w_v);
    qk_kernel<<<dim3(8, 8, 32), 256>>>();
    mixsm_kernel<<<dim3(1024, 4), 256>>>(w_head);
    vsum_kernel<<<2048, 256>>>();
    finalize_kernel<<<32, 256>>>(in_gamma, in_beta);
    av_kernel<<<dim3(8, 32), 256>>>();
    proj_kernel<<<dim3(8, 4, 4), 256>>>(w_proj, b_proj, outF);
}

// round 3
// speedup vs baseline: 2.1530x; 1.4270x over previous
#include <cuda_runtime.h>
#include <math.h>
#include <stdint.h>

#define NB 4
#define NC 512
#define NT 1024
#define NHEADS 8
#define NHD 64
#define EPS_IN 1e-5f

// ---------------- device scratch ----------------
__device__ float g_q[NB * NC * NT];                       // [b][o][t]
__device__ float g_k[NB * NC * NT];
__device__ float g_v[NB * NC * NT];
__device__ float g_attn[(size_t)NB * NHEADS * NT * NT];   // [bh][q][T] 134MB
__device__ float g_out[NB * NHEADS * NT * NHD];           // [bh][q][d] == [b][t][c]
__device__ float g_vsum[NB * NC];
__device__ float g_rowsq[NB * NHEADS * NT];
__device__ float g_alpha[32];
__device__ float g_betac[32];

// ---------------- tf32 helpers ----------------
__device__ __forceinline__ uint32_t f2tf(float f) {
    uint32_t u;
    asm("cvt.rna.tf32.f32 %0, %1;" : "=r"(u) : "f"(f));
    return u;
}
__device__ __forceinline__ void mma8(float* c, const uint32_t* a, const uint32_t* b) {
    asm volatile("mma.sync.aligned.m16n8k8.row.col.f32.tf32.tf32.f32 "
        "{%0,%1,%2,%3}, {%4,%5,%6,%7}, {%8,%9}, {%0,%1,%2,%3};\n"
        : "+f"(c[0]), "+f"(c[1]), "+f"(c[2]), "+f"(c[3])
        : "r"(a[0]), "r"(a[1]), "r"(a[2]), "r"(a[3]), "r"(b[0]), "r"(b[1]));
}

// ============ Kernel 1: QKV. out[o,t] = sum_c W[o,c] x[c,t] ============
// M=512(o) N=1024(t) K=512. Block 128x128, BK=32, warps 2x4 (64x32).
__global__ __launch_bounds__(256) void qkv_tf32(const float* __restrict__ x,
                                                const float* __restrict__ wq,
                                                const float* __restrict__ wk,
                                                const float* __restrict__ wv) {
    int z = blockIdx.z;
    int b = z / 3, which = z - b * 3;
    const float* W = (which == 0) ? wq : (which == 1) ? wk : wv;
    float* out = ((which == 0) ? g_q : (which == 1) ? g_k : g_v) + (size_t)b * NC * NT;
    const float* X = x + (size_t)b * NC * NT;

    int oBase = blockIdx.y * 128;
    int tBase = blockIdx.x * 128;

    __shared__ uint32_t As[128][36];   // [o][c]
    __shared__ uint32_t Bs[128][36];   // [t][c]

    int tid = threadIdx.x, lane = tid & 31, wid = tid >> 5;
    int wm = wid >> 2, wn = wid & 3;
    int lr = lane >> 2, lk = lane & 3;

    float acc[4][4][4];
#pragma unroll
    for (int mi = 0; mi < 4; mi++)
#pragma unroll
        for (int nj = 0; nj < 4; nj++)
#pragma unroll
            for (int cidx = 0; cidx < 4; cidx++) acc[mi][nj][cidx] = 0.f;

    for (int k0 = 0; k0 < NC; k0 += 32) {
#pragma unroll
        for (int i = 0; i < 4; i++) {
            int idx = tid + i * 256;
            int o = idx >> 3, c4 = (idx & 7) * 4;
            float4 w4 = *(const float4*)&W[(size_t)(oBase + o) * NC + k0 + c4];
            *(uint4*)&As[o][c4] = make_uint4(f2tf(w4.x), f2tf(w4.y), f2tf(w4.z), f2tf(w4.w));
        }
#pragma unroll
        for (int i = 0; i < 4; i++) {
            int idx = tid + i * 256;
            int c = idx >> 5, t4 = (idx & 31) * 4;
            float4 x4 = *(const float4*)&X[(size_t)(k0 + c) * NT + tBase + t4];
            Bs[t4 + 0][c] = f2tf(x4.x);
            Bs[t4 + 1][c] = f2tf(x4.y);
            Bs[t4 + 2][c] = f2tf(x4.z);
            Bs[t4 + 3][c] = f2tf(x4.w);
        }
        __syncthreads();
#pragma unroll
        for (int kk = 0; kk < 32; kk += 8) {
            uint32_t af[4][4], bf[4][2];
#pragma unroll
            for (int mi = 0; mi < 4; mi++) {
                int m0 = wm * 64 + mi * 16 + lr;
                af[mi][0] = As[m0][kk + lk];
                af[mi][1] = As[m0 + 8][kk + lk];
                af[mi][2] = As[m0][kk + lk + 4];
                af[mi][3] = As[m0 + 8][kk + lk + 4];
            }
#pragma unroll
            for (int nj = 0; nj < 4; nj++) {
                int n0 = wn * 32 + nj * 8 + lr;
                bf[nj][0] = Bs[n0][kk + lk];
                bf[nj][1] = Bs[n0][kk + lk + 4];
            }
#pragma unroll
            for (int mi = 0; mi < 4; mi++)
#pragma unroll
                for (int nj = 0; nj < 4; nj++) mma8(acc[mi][nj], af[mi], bf[nj]);
        }
        __syncthreads();
    }
#pragma unroll
    for (int mi = 0; mi < 4; mi++) {
        int r = oBase + wm * 64 + mi * 16 + lr;
#pragma unroll
        for (int nj = 0; nj < 4; nj++) {
            int cc = tBase + wn * 32 + nj * 8 + lk * 2;
            *(float2*)&out[(size_t)r * NT + cc] = make_float2(acc[mi][nj][0], acc[mi][nj][1]);
            *(float2*)&out[(size_t)(r + 8) * NT + cc] = make_float2(acc[mi][nj][2], acc[mi][nj][3]);
        }
    }
}

// ============ Kernel 2: QK^T. attn[q,T] = 0.125 * sum_d q[d,q] k[d,T] ============
// M=N=1024, K=64 per (b,h). Block 128x128, BK=32 (2 chunks), warps 2x4.
__global__ __launch_bounds__(256) void qk_tf32() {
    int bh = blockIdx.z;
    int b = bh >> 3, h = bh & 7;
    const float* A = g_q + (size_t)(b * NC + h * NHD) * NT;   // [d][q]
    const float* Bm = g_k + (size_t)(b * NC + h * NHD) * NT;  // [d][T]
    float* out = g_attn + (size_t)bh * NT * NT;

    int qBase = blockIdx.y * 128;
    int tBase = blockIdx.x * 128;

    __shared__ uint32_t As[128][36];   // [q][d]
    __shared__ uint32_t Bs[128][36];   // [T][d]

    int tid = threadIdx.x, lane = tid & 31, wid = tid >> 5;
    int wm = wid >> 2, wn = wid & 3;
    int lr = lane >> 2, lk = lane & 3;

    float acc[4][4][4];
#pragma unroll
    for (int mi = 0; mi < 4; mi++)
#pragma unroll
        for (int nj = 0; nj < 4; nj++)
#pragma unroll
            for (int cidx = 0; cidx < 4; cidx++) acc[mi][nj][cidx] = 0.f;

    for (int k0 = 0; k0 < NHD; k0 += 32) {
#pragma unroll
        for (int i = 0; i < 4; i++) {
            int idx = tid + i * 256;
            int d = idx >> 5, m4 = (idx & 31) * 4;
            float4 a4 = *(const float4*)&A[(size_t)(k0 + d) * NT + qBase + m4];
            As[m4 + 0][d] = f2tf(a4.x);
            As[m4 + 1][d] = f2tf(a4.y);
            As[m4 + 2][d] = f2tf(a4.z);
            As[m4 + 3][d] = f2tf(a4.w);
            float4 b4 = *(const float4*)&Bm[(size_t)(k0 + d) * NT + tBase + m4];
            Bs[m4 + 0][d] = f2tf(b4.x);
            Bs[m4 + 1][d] = f2tf(b4.y);
            Bs[m4 + 2][d] = f2tf(b4.z);
            Bs[m4 + 3][d] = f2tf(b4.w);
        }
        __syncthreads();
#pragma unroll
        for (int kk = 0; kk < 32; kk += 8) {
            uint32_t af[4][4], bf[4][2];
#pragma unroll
            for (int mi = 0; mi < 4; mi++) {
                int m0 = wm * 64 + mi * 16 + lr;
                af[mi][0] = As[m0][kk + lk];
                af[mi][1] = As[m0 + 8][kk + lk];
                af[mi][2] = As[m0][kk + lk + 4];
                af[mi][3] = As[m0 + 8][kk + lk + 4];
            }
#pragma unroll
            for (int nj = 0; nj < 4; nj++) {
                int n0 = wn * 32 + nj * 8 + lr;
                bf[nj][0] = Bs[n0][kk + lk];
                bf[nj][1] = Bs[n0][kk + lk + 4];
            }
#pragma unroll
            for (int mi = 0; mi < 4; mi++)
#pragma unroll
                for (int nj = 0; nj < 4; nj++) mma8(acc[mi][nj], af[mi], bf[nj]);
        }
        __syncthreads();
    }
#pragma unroll
    for (int mi = 0; mi < 4; mi++) {
        int r = qBase + wm * 64 + mi * 16 + lr;
#pragma unroll
        for (int nj = 0; nj < 4; nj++) {
            int cc = tBase + wn * 32 + nj * 8 + lk * 2;
            *(float2*)&out[(size_t)r * NT + cc] =
                make_float2(acc[mi][nj][0] * 0.125f, acc[mi][nj][1] * 0.125f);
            *(float2*)&out[(size_t)(r + 8) * NT + cc] =
                make_float2(acc[mi][nj][2] * 0.125f, acc[mi][nj][3] * 0.125f);
        }
    }
}

// ============ Kernel 3: head-mix + softmax + row sumsq (in place) ============
__global__ __launch_bounds__(256) void mixsm_kernel(const float* __restrict__ w_head) {
    int q = blockIdx.x, b = blockIdx.y;
    __shared__ float raw[8][NT];

    for (int idx = threadIdx.x; idx < 8 * NT / 4; idx += 256) {
        int h = idx >> 8, t4 = (idx & 255) * 4;
        *(float4*)&raw[h][t4] =
            *(const float4*)&g_attn[(((size_t)(b * 8 + h)) * NT + q) * NT + t4];
    }
    __syncthreads();

    int g = threadIdx.x >> 5, lane = threadIdx.x & 31;
    float wh[8];
#pragma unroll
    for (int h = 0; h < 8; h++) wh[h] = w_head[g * 8 + h];

    float vals[32];
    float mx = -1e30f;
#pragma unroll
    for (int i = 0; i < 32; i++) {
        int Tt = i * 32 + lane;
        float m = 0.f;
#pragma unroll
        for (int h = 0; h < 8; h++) m += wh[h] * raw[h][Tt];
        vals[i] = m;
        mx = fmaxf(mx, m);
    }
#pragma unroll
    for (int off = 16; off > 0; off >>= 1)
        mx = fmaxf(mx, __shfl_xor_sync(0xffffffffu, mx, off));

    float s = 0.f, s2 = 0.f;
#pragma unroll
    for (int i = 0; i < 32; i++) {
        vals[i] = __expf(vals[i] - mx);
        s += vals[i];
        s2 += vals[i] * vals[i];
    }
#pragma unroll
    for (int off = 16; off > 0; off >>= 1) {
        s  += __shfl_xor_sync(0xffffffffu, s, off);
        s2 += __shfl_xor_sync(0xffffffffu, s2, off);
    }

    float inv = 1.f / s;
    size_t base = (((size_t)(b * 8 + g)) * NT + q) * NT;
#pragma unroll
    for (int i = 0; i < 32; i++)
        g_attn[base + i * 32 + lane] = vals[i] * inv;

    if (lane == 0)
        g_rowsq[(b * 8 + g) * NT + q] = s2 * inv * inv;
}

// ============ Kernel 4: vsum ============
__global__ __launch_bounds__(256) void vsum_kernel() {
    __shared__ float sbuf[8];
    int row = blockIdx.x;
    float4 p = *(const float4*)&g_v[(size_t)row * NT + threadIdx.x * 4];
    float s = p.x + p.y + p.z + p.w;
    int lane = threadIdx.x & 31, w = threadIdx.x >> 5;
#pragma unroll
    for (int o = 16; o > 0; o >>= 1) s += __shfl_xor_sync(0xffffffffu, s, o);
    if (lane == 0) sbuf[w] = s;
    __syncthreads();
    if (threadIdx.x == 0) {
        float t = 0.f;
        for (int i = 0; i < 8; i++) t += sbuf[i];
        g_vsum[row] = t;
    }
}

// ============ Kernel 5: finalize InstanceNorm params ============
__global__ __launch_bounds__(256) void finalize_kernel(const float* __restrict__ gamma,
                                                       const float* __restrict__ beta) {
    __shared__ float sbuf[8];
    int grp = blockIdx.x;
    float s = 0.f;
    for (int i = threadIdx.x; i < NT; i += 256) s += g_rowsq[grp * NT + i];
    int lane = threadIdx.x & 31, w = threadIdx.x >> 5;
#pragma unroll
    for (int o = 16; o > 0; o >>= 1) s += __shfl_xor_sync(0xffffffffu, s, o);
    if (lane == 0) sbuf[w] = s;
    __syncthreads();
    if (threadIdx.x == 0) {
        float sumsq = 0.f;
        for (int i = 0; i < 8; i++) sumsq += sbuf[i];
        const float invN = 1.f / (1024.f * 1024.f);
        float mean = 1.f / 1024.f;
        float var = sumsq * invN - mean * mean;
        int h = grp & 7;
        float alpha = gamma[h] * rsqrtf(var + EPS_IN);
        g_alpha[grp] = alpha;
        g_betac[grp] = beta[h] - alpha * mean;
    }
}

// ============ Kernel 6: AV + folded InstanceNorm ============
// out[q,d] = alpha * sum_T attn[q,T] v[d,T] + betac * vsum[d]
// M=1024(q) N=64(d) K=1024. Block 128x64, BK=32, warps 4x2 (32x32).
__global__ __launch_bounds__(256) void av_tf32() {
    int bh = blockIdx.y;
    int b = bh >> 3, h = bh & 7;
    const float* A = g_attn + (size_t)bh * NT * NT;              // [q][T]
    const float* V = g_v + (size_t)(b * NC + h * NHD) * NT;      // [d][T]
    float* out = g_out + (size_t)bh * NT * NHD;
    int qBase = blockIdx.x * 128;

    __shared__ uint32_t As[128][36];   // [q][T]
    __shared__ uint32_t Bs[64][36];    // [d][T]

    int tid = threadIdx.x, lane = tid & 31, wid = tid >> 5;
    int wm = wid >> 1, wn = wid & 1;
    int lr = lane >> 2, lk = lane & 3;

    float acc[2][4][4];
#pragma unroll
    for (int mi = 0; mi < 2; mi++)
#pragma unroll
        for (int nj = 0; nj < 4; nj++)
#pragma unroll
            for (int cidx = 0; cidx < 4; cidx++) acc[mi][nj][cidx] = 0.f;

    for (int k0 = 0; k0 < NT; k0 += 32) {
#pragma unroll
        for (int i = 0; i < 4; i++) {
            int idx = tid + i * 256;
            int q = idx >> 3, t4 = (idx & 7) * 4;
            float4 a4 = *(const float4*)&A[(size_t)(qBase + q) * NT + k0 + t4];
            *(uint4*)&As[q][t4] = make_uint4(f2tf(a4.x), f2tf(a4.y), f2tf(a4.z), f2tf(a4.w));
        }
#pragma unroll
        for (int i = 0; i < 2; i++) {
            int idx = tid + i * 256;
            int d = idx >> 3, t4 = (idx & 7) * 4;
            float4 v4 = *(const float4*)&V[(size_t)d * NT + k0 + t4];
            *(uint4*)&Bs[d][t4] = make_uint4(f2tf(v4.x), f2tf(v4.y), f2tf(v4.z), f2tf(v4.w));
        }
        __syncthreads();
#pragma unroll
        for (int kk = 0; kk < 32; kk += 8) {
            uint32_t af[2][4], bf[4][2];
#pragma unroll
            for (int mi = 0; mi < 2; mi++) {
                int m0 = wm * 32 + mi * 16 + lr;
                af[mi][0] = As[m0][kk + lk];
                af[mi][1] = As[m0 + 8][kk + lk];
                af[mi][2] = As[m0][kk + lk + 4];
                af[mi][3] = As[m0 + 8][kk + lk + 4];
            }
#pragma unroll
            for (int nj = 0; nj < 4; nj++) {
                int n0 = wn * 32 + nj * 8 + lr;
                bf[nj][0] = Bs[n0][kk + lk];
                bf[nj][1] = Bs[n0][kk + lk + 4];
            }
#pragma unroll
            for (int mi = 0; mi < 2; mi++)
#pragma unroll
                for (int nj = 0; nj < 4; nj++) mma8(acc[mi][nj], af[mi], bf[nj]);
        }
        __syncthreads();
    }

    float alpha = g_alpha[bh], bc = g_betac[bh];
#pragma unroll
    for (int mi = 0; mi < 2; mi++) {
        int r = qBase + wm * 32 + mi * 16 + lr;
#pragma unroll
        for (int nj = 0; nj < 4; nj++) {
            int d0 = wn * 32 + nj * 8 + lk * 2;
            float vs0 = g_vsum[bh * NHD + d0], vs1 = g_vsum[bh * NHD + d0 + 1];
            *(float2*)&out[(size_t)r * NHD + d0] =
                make_float2(alpha * acc[mi][nj][0] + bc * vs0,
                            alpha * acc[mi][nj][1] + bc * vs1);
            *(float2*)&out[(size_t)(r + 8) * NHD + d0] =
                make_float2(alpha * acc[mi][nj][2] + bc * vs0,
                            alpha * acc[mi][nj][3] + bc * vs1);
        }
    }
}

// ============ Kernel 7: projection. final[co,t] = sum_c mid[t,c] W[co,c] + bias ============
// M=512(co) N=1024(t) K=512. Block 128x128, BK=32, warps 2x4.
__global__ __launch_bounds__(256) void proj_tf32(const float* __restrict__ w_proj,
                                                 const float* __restrict__ b_proj,
                                                 float* __restrict__ outF) {
    int b = blockIdx.z;
    int coBase = blockIdx.y * 128;
    int tBase = blockIdx.x * 128;
    const float* mid = g_out + (size_t)b * NT * NC;   // [t][c]

    __shared__ uint32_t As[128][36];   // [co][c]
    __shared__ uint32_t Bs[128][36];   // [t][c]

    int tid = threadIdx.x, lane = tid & 31, wid = tid >> 5;
    int wm = wid >> 2, wn = wid & 3;
    int lr = lane >> 2, lk = lane & 3;

    float acc[4][4][4];
#pragma unroll
    for (int mi = 0; mi < 4; mi++)
#pragma unroll
        for (int nj = 0; nj < 4; nj++)
#pragma unroll
            for (int cidx = 0; cidx < 4; cidx++) acc[mi][nj][cidx] = 0.f;

    for (int k0 = 0; k0 < NC; k0 += 32) {
#pragma unroll
        for (int i = 0; i < 4; i++) {
            int idx = tid + i * 256;
            int r = idx >> 3, c4 = (idx & 7) * 4;
            float4 w4 = *(const float4*)&w_proj[(size_t)(coBase + r) * NC + k0 + c4];
            *(uint4*)&As[r][c4] = make_uint4(f2tf(w4.x), f2tf(w4.y), f2tf(w4.z), f2tf(w4.w));
            float4 m4 = *(const float4*)&mid[(size_t)(tBase + r) * NC + k0 + c4];
            *(uint4*)&Bs[r][c4] = make_uint4(f2tf(m4.x), f2tf(m4.y), f2tf(m4.z), f2tf(m4.w));
        }
        __syncthreads();
#pragma unroll
        for (int kk = 0; kk < 32; kk += 8) {
            uint32_t af[4][4], bf[4][2];
#pragma unroll
            for (int mi = 0; mi < 4; mi++) {
                int m0 = wm * 64 + mi * 16 + lr;
                af[mi][0] = As[m0][kk + lk];
                af[mi][1] = As[m0 + 8][kk + lk];
                af[mi][2] = As[m0][kk + lk + 4];
                af[mi][3] = As[m0 + 8][kk + lk + 4];
            }
#pragma unroll
            for (int nj = 0; nj < 4; nj++) {
                int n0 = wn * 32 + nj * 8 + lr;
                bf[nj][0] = Bs[n0][kk + lk];
                bf[nj][1] = Bs[n0][kk + lk + 4];
            }
#pragma unroll
            for (int mi = 0; mi < 4; mi++)
#pragma unroll
                for (int nj = 0; nj < 4; nj++) mma8(acc[mi][nj], af[mi], bf[nj]);
        }
        __syncthreads();
    }
#pragma unroll
    for (int mi = 0; mi < 4; mi++) {
        int co = coBase + wm * 64 + mi * 16 + lr;
        float bias0 = b_proj[co], bias1 = b_proj[co + 8];
        float* op0 = outF + (size_t)b * NC * NT + (size_t)co * NT;
        float* op1 = op0 + (size_t)8 * NT;
#pragma unroll
        for (int nj = 0; nj < 4; nj++) {
            int cc = tBase + wn * 32 + nj * 8 + lk * 2;
            *(float2*)&op0[cc] = make_float2(acc[mi][nj][0] + bias0, acc[mi][nj][1] + bias0);
            *(float2*)&op1[cc] = make_float2(acc[mi][nj][2] + bias1, acc[mi][nj][3] + bias1);
        }
    }
}

// ---------------- launch ----------------
extern "C" void kernel_launch(void* const* d_in, const int* in_sizes, int n_in,
                              void* d_out, int out_size) {
    (void)in_sizes; (void)n_in; (void)out_size;
    const float* x        = (const float*)d_in[0];
    const float* w_q      = (const float*)d_in[1];
    const float* w_k      = (const float*)d_in[2];
    const float* w_v      = (const float*)d_in[3];
    const float* w_head   = (const float*)d_in[4];
    const float* in_gamma = (const float*)d_in[5];
    const float* in_beta  = (const float*)d_in[6];
    const float* w_proj   = (const float*)d_in[7];
    const float* b_proj   = (const float*)d_in[8];
    float* outF = (float*)d_out;

    qkv_tf32<<<dim3(8, 4, 12), 256>>>(x, w_q, w_k, w_v);
    qk_tf32<<<dim3(8, 8, 32), 256>>>();
    mixsm_kernel<<<dim3(1024, 4), 256>>>(w_head);
    vsum_kernel<<<2048, 256>>>();
    finalize_kernel<<<32, 256>>>(in_gamma, in_beta);
    av_tf32<<<dim3(8, 32), 256>>>();
    proj_tf32<<<dim3(8, 4, 4), 256>>>(w_proj, b_proj, outF);
}

// round 4
// speedup vs baseline: 2.4719x; 1.1481x over previous
#include <cuda_runtime.h>
#include <cuda_fp16.h>
#include <math.h>
#include <stdint.h>

#define NB 4
#define NC 512
#define NT 1024
#define NHEADS 8
#define NHD 64
#define EPS_IN 1e-5f

// ---------------- device scratch ----------------
__device__ float g_q[NB * NC * NT];
__device__ float g_k[NB * NC * NT];
__device__ float g_v[NB * NC * NT];
__device__ __half g_vh[NB * NC * NT];                       // fp16 shadow of v
__device__ float g_attn[(size_t)NB * NHEADS * NT * NT];     // raw logits fp32 134MB
__device__ __half g_ph[(size_t)NB * NHEADS * NT * NT];      // softmax probs fp16 67MB
__device__ float g_out[NB * NHEADS * NT * NHD];             // == [b][t][c]
__device__ float g_vsum[NB * NC];
__device__ float g_rowsq[NB * NHEADS * NT];
__device__ float g_alpha[32];
__device__ float g_betac[32];

// ---------------- mma helpers ----------------
__device__ __forceinline__ uint32_t f2tf(float f) {
    uint32_t u;
    asm("cvt.rna.tf32.f32 %0, %1;" : "=r"(u) : "f"(f));
    return u;
}
__device__ __forceinline__ void mma8(float* c, const uint32_t* a, const uint32_t* b) {
    asm volatile("mma.sync.aligned.m16n8k8.row.col.f32.tf32.tf32.f32 "
        "{%0,%1,%2,%3}, {%4,%5,%6,%7}, {%8,%9}, {%0,%1,%2,%3};\n"
        : "+f"(c[0]), "+f"(c[1]), "+f"(c[2]), "+f"(c[3])
        : "r"(a[0]), "r"(a[1]), "r"(a[2]), "r"(a[3]), "r"(b[0]), "r"(b[1]));
}
__device__ __forceinline__ void mma16h(float* c, const uint32_t* a, const uint32_t* b) {
    asm volatile("mma.sync.aligned.m16n8k16.row.col.f32.f16.f16.f32 "
        "{%0,%1,%2,%3}, {%4,%5,%6,%7}, {%8,%9}, {%0,%1,%2,%3};\n"
        : "+f"(c[0]), "+f"(c[1]), "+f"(c[2]), "+f"(c[3])
        : "r"(a[0]), "r"(a[1]), "r"(a[2]), "r"(a[3]), "r"(b[0]), "r"(b[1]));
}

// ============ Kernel 1: QKV. out[o,t] = sum_c W[o,c] x[c,t] ============
__global__ __launch_bounds__(256) void qkv_tf32(const float* __restrict__ x,
                                                const float* __restrict__ wq,
                                                const float* __restrict__ wk,
                                                const float* __restrict__ wv) {
    int z = blockIdx.z;
    int b = z / 3, which = z - b * 3;
    const float* W = (which == 0) ? wq : (which == 1) ? wk : wv;
    float* out = ((which == 0) ? g_q : (which == 1) ? g_k : g_v) + (size_t)b * NC * NT;
    const float* X = x + (size_t)b * NC * NT;

    int oBase = blockIdx.y * 128;
    int tBase = blockIdx.x * 128;

    __shared__ uint32_t As[128][36];   // [o][c]
    __shared__ uint32_t Bs[128][36];   // [t][c]

    int tid = threadIdx.x, lane = tid & 31, wid = tid >> 5;
    int wm = wid >> 2, wn = wid & 3;
    int lr = lane >> 2, lk = lane & 3;

    float acc[4][4][4];
#pragma unroll
    for (int mi = 0; mi < 4; mi++)
#pragma unroll
        for (int nj = 0; nj < 4; nj++)
#pragma unroll
            for (int ci = 0; ci < 4; ci++) acc[mi][nj][ci] = 0.f;

    for (int k0 = 0; k0 < NC; k0 += 32) {
#pragma unroll
        for (int i = 0; i < 4; i++) {
            int idx = tid + i * 256;
            int o = idx >> 3, c4 = (idx & 7) * 4;
            float4 w4 = *(const float4*)&W[(size_t)(oBase + o) * NC + k0 + c4];
            *(uint4*)&As[o][c4] = make_uint4(f2tf(w4.x), f2tf(w4.y), f2tf(w4.z), f2tf(w4.w));
        }
#pragma unroll
        for (int i = 0; i < 4; i++) {
            int idx = tid + i * 256;
            int c = idx >> 5, t4 = (idx & 31) * 4;
            float4 x4 = *(const float4*)&X[(size_t)(k0 + c) * NT + tBase + t4];
            Bs[t4 + 0][c] = f2tf(x4.x);
            Bs[t4 + 1][c] = f2tf(x4.y);
            Bs[t4 + 2][c] = f2tf(x4.z);
            Bs[t4 + 3][c] = f2tf(x4.w);
        }
        __syncthreads();
#pragma unroll
        for (int kk = 0; kk < 32; kk += 8) {
            uint32_t af[4][4], bf[4][2];
#pragma unroll
            for (int mi = 0; mi < 4; mi++) {
                int m0 = wm * 64 + mi * 16 + lr;
                af[mi][0] = As[m0][kk + lk];
                af[mi][1] = As[m0 + 8][kk + lk];
                af[mi][2] = As[m0][kk + lk + 4];
                af[mi][3] = As[m0 + 8][kk + lk + 4];
            }
#pragma unroll
            for (int nj = 0; nj < 4; nj++) {
                int n0 = wn * 32 + nj * 8 + lr;
                bf[nj][0] = Bs[n0][kk + lk];
                bf[nj][1] = Bs[n0][kk + lk + 4];
            }
#pragma unroll
            for (int mi = 0; mi < 4; mi++)
#pragma unroll
                for (int nj = 0; nj < 4; nj++) mma8(acc[mi][nj], af[mi], bf[nj]);
        }
        __syncthreads();
    }
#pragma unroll
    for (int mi = 0; mi < 4; mi++) {
        int r = oBase + wm * 64 + mi * 16 + lr;
#pragma unroll
        for (int nj = 0; nj < 4; nj++) {
            int cc = tBase + wn * 32 + nj * 8 + lk * 2;
            *(float2*)&out[(size_t)r * NT + cc] = make_float2(acc[mi][nj][0], acc[mi][nj][1]);
            *(float2*)&out[(size_t)(r + 8) * NT + cc] = make_float2(acc[mi][nj][2], acc[mi][nj][3]);
        }
    }
    if (which == 2) {
        __half* vh = g_vh + (size_t)b * NC * NT;
#pragma unroll
        for (int mi = 0; mi < 4; mi++) {
            int r = oBase + wm * 64 + mi * 16 + lr;
#pragma unroll
            for (int nj = 0; nj < 4; nj++) {
                int cc = tBase + wn * 32 + nj * 8 + lk * 2;
                *(__half2*)&vh[(size_t)r * NT + cc] =
                    __floats2half2_rn(acc[mi][nj][0], acc[mi][nj][1]);
                *(__half2*)&vh[(size_t)(r + 8) * NT + cc] =
                    __floats2half2_rn(acc[mi][nj][2], acc[mi][nj][3]);
            }
        }
    }
}

// ============ Kernel 2: QK^T. attn[q,T] = 0.125 * sum_d q[d,q] k[d,T] ============
__global__ __launch_bounds__(256) void qk_tf32() {
    int bh = blockIdx.z;
    int b = bh >> 3, h = bh & 7;
    const float* A = g_q + (size_t)(b * NC + h * NHD) * NT;
    const float* Bm = g_k + (size_t)(b * NC + h * NHD) * NT;
    float* out = g_attn + (size_t)bh * NT * NT;

    int qBase = blockIdx.y * 128;
    int tBase = blockIdx.x * 128;

    __shared__ uint32_t As[128][36];
    __shared__ uint32_t Bs[128][36];

    int tid = threadIdx.x, lane = tid & 31, wid = tid >> 5;
    int wm = wid >> 2, wn = wid & 3;
    int lr = lane >> 2, lk = lane & 3;

    float acc[4][4][4];
#pragma unroll
    for (int mi = 0; mi < 4; mi++)
#pragma unroll
        for (int nj = 0; nj < 4; nj++)
#pragma unroll
            for (int ci = 0; ci < 4; ci++) acc[mi][nj][ci] = 0.f;

    for (int k0 = 0; k0 < NHD; k0 += 32) {
#pragma unroll
        for (int i = 0; i < 4; i++) {
            int idx = tid + i * 256;
            int d = idx >> 5, m4 = (idx & 31) * 4;
            float4 a4 = *(const float4*)&A[(size_t)(k0 + d) * NT + qBase + m4];
            As[m4 + 0][d] = f2tf(a4.x);
            As[m4 + 1][d] = f2tf(a4.y);
            As[m4 + 2][d] = f2tf(a4.z);
            As[m4 + 3][d] = f2tf(a4.w);
            float4 b4 = *(const float4*)&Bm[(size_t)(k0 + d) * NT + tBase + m4];
            Bs[m4 + 0][d] = f2tf(b4.x);
            Bs[m4 + 1][d] = f2tf(b4.y);
            Bs[m4 + 2][d] = f2tf(b4.z);
            Bs[m4 + 3][d] = f2tf(b4.w);
        }
        __syncthreads();
#pragma unroll
        for (int kk = 0; kk < 32; kk += 8) {
            uint32_t af[4][4], bf[4][2];
#pragma unroll
            for (int mi = 0; mi < 4; mi++) {
                int m0 = wm * 64 + mi * 16 + lr;
                af[mi][0] = As[m0][kk + lk];
                af[mi][1] = As[m0 + 8][kk + lk];
                af[mi][2] = As[m0][kk + lk + 4];
                af[mi][3] = As[m0 + 8][kk + lk + 4];
            }
#pragma unroll
            for (int nj = 0; nj < 4; nj++) {
                int n0 = wn * 32 + nj * 8 + lr;
                bf[nj][0] = Bs[n0][kk + lk];
                bf[nj][1] = Bs[n0][kk + lk + 4];
            }
#pragma unroll
            for (int mi = 0; mi < 4; mi++)
#pragma unroll
                for (int nj = 0; nj < 4; nj++) mma8(acc[mi][nj], af[mi], bf[nj]);
        }
        __syncthreads();
    }
#pragma unroll
    for (int mi = 0; mi < 4; mi++) {
        int r = qBase + wm * 64 + mi * 16 + lr;
#pragma unroll
        for (int nj = 0; nj < 4; nj++) {
            int cc = tBase + wn * 32 + nj * 8 + lk * 2;
            *(float2*)&out[(size_t)r * NT + cc] =
                make_float2(acc[mi][nj][0] * 0.125f, acc[mi][nj][1] * 0.125f);
            *(float2*)&out[(size_t)(r + 8) * NT + cc] =
                make_float2(acc[mi][nj][2] * 0.125f, acc[mi][nj][3] * 0.125f);
        }
    }
}

// ============ Kernel 3: head-mix + softmax (registers) -> fp16 probs ============
// Block = (q, b). Thread t owns T positions 4t..4t+3 for all 8 mixed heads.
__global__ __launch_bounds__(256) void mixsm_kernel(const float* __restrict__ w_head) {
    int q = blockIdx.x, b = blockIdx.y;
    int t = threadIdx.x;
    int lane = t & 31, wid = t >> 5;

    __shared__ float wh[64];
    __shared__ float red[8][36];
    __shared__ float red2[8][36];
    __shared__ float fin[8], fin2[8];

    if (t < 64) wh[t] = w_head[t];
    __syncthreads();

    float raw[8][4];
#pragma unroll
    for (int h = 0; h < 8; h++) {
        float4 r4 = *(const float4*)&g_attn[(((size_t)(b * 8 + h)) * NT + q) * NT + t * 4];
        raw[h][0] = r4.x; raw[h][1] = r4.y; raw[h][2] = r4.z; raw[h][3] = r4.w;
    }

    float m[8][4];
#pragma unroll
    for (int g = 0; g < 8; g++) {
#pragma unroll
        for (int j = 0; j < 4; j++) {
            float acc = 0.f;
#pragma unroll
            for (int h = 0; h < 8; h++) acc += wh[g * 8 + h] * raw[h][j];
            m[g][j] = acc;
        }
    }

    // block max per g: 3-step warp partial -> 32-wide second stage
#pragma unroll
    for (int g = 0; g < 8; g++) {
        float v = fmaxf(fmaxf(m[g][0], m[g][1]), fmaxf(m[g][2], m[g][3]));
        v = fmaxf(v, __shfl_xor_sync(0xffffffffu, v, 16));
        v = fmaxf(v, __shfl_xor_sync(0xffffffffu, v, 8));
        v = fmaxf(v, __shfl_xor_sync(0xffffffffu, v, 4));
        if (lane < 4) red[g][wid * 4 + lane] = v;
    }
    __syncthreads();
    {
        int g = t >> 5;
        float v = red[g][lane];
        v = fmaxf(v, __shfl_xor_sync(0xffffffffu, v, 16));
        v = fmaxf(v, __shfl_xor_sync(0xffffffffu, v, 8));
        v = fmaxf(v, __shfl_xor_sync(0xffffffffu, v, 4));
        v = fmaxf(v, __shfl_xor_sync(0xffffffffu, v, 2));
        v = fmaxf(v, __shfl_xor_sync(0xffffffffu, v, 1));
        if (lane == 0) fin[g] = v;
    }
    __syncthreads();

    float s[8], s2[8];
#pragma unroll
    for (int g = 0; g < 8; g++) {
        float mx = fin[g];
        float e0 = __expf(m[g][0] - mx);
        float e1 = __expf(m[g][1] - mx);
        float e2 = __expf(m[g][2] - mx);
        float e3 = __expf(m[g][3] - mx);
        m[g][0] = e0; m[g][1] = e1; m[g][2] = e2; m[g][3] = e3;
        s[g] = (e0 + e1) + (e2 + e3);
        s2[g] = (e0 * e0 + e1 * e1) + (e2 * e2 + e3 * e3);
    }
    __syncthreads();

#pragma unroll
    for (int g = 0; g < 8; g++) {
        float v = s[g], w2 = s2[g];
        v += __shfl_xor_sync(0xffffffffu, v, 16);
        w2 += __shfl_xor_sync(0xffffffffu, w2, 16);
        v += __shfl_xor_sync(0xffffffffu, v, 8);
        w2 += __shfl_xor_sync(0xffffffffu, w2, 8);
        v += __shfl_xor_sync(0xffffffffu, v, 4);
        w2 += __shfl_xor_sync(0xffffffffu, w2, 4);
        if (lane < 4) { red[g][wid * 4 + lane] = v; red2[g][wid * 4 + lane] = w2; }
    }
    __syncthreads();
    {
        int g = t >> 5;
        float v = red[g][lane], w2 = red2[g][lane];
        v += __shfl_xor_sync(0xffffffffu, v, 16);
        w2 += __shfl_xor_sync(0xffffffffu, w2, 16);
        v += __shfl_xor_sync(0xffffffffu, v, 8);
        w2 += __shfl_xor_sync(0xffffffffu, w2, 8);
        v += __shfl_xor_sync(0xffffffffu, v, 4);
        w2 += __shfl_xor_sync(0xffffffffu, w2, 4);
        v += __shfl_xor_sync(0xffffffffu, v, 2);
        w2 += __shfl_xor_sync(0xffffffffu, w2, 2);
        v += __shfl_xor_sync(0xffffffffu, v, 1);
        w2 += __shfl_xor_sync(0xffffffffu, w2, 1);
        if (lane == 0) { fin[g] = v; fin2[g] = w2; }
    }
    __syncthreads();

#pragma unroll
    for (int g = 0; g < 8; g++) {
        float inv = 1.f / fin[g];
        __half2 h0 = __floats2half2_rn(m[g][0] * inv, m[g][1] * inv);
        __half2 h1 = __floats2half2_rn(m[g][2] * inv, m[g][3] * inv);
        uint2 u;
        u.x = *(uint32_t*)&h0;
        u.y = *(uint32_t*)&h1;
        *(uint2*)&g_ph[(((size_t)(b * 8 + g)) * NT + q) * NT + t * 4] = u;
    }
    if (t < 8) {
        float sv = fin[t];
        g_rowsq[(b * 8 + t) * NT + q] = fin2[t] / (sv * sv);
    }
}

// ============ Kernel 4: vsum ============
__global__ __launch_bounds__(256) void vsum_kernel() {
    __shared__ float sbuf[8];
    int row = blockIdx.x;
    float4 p = *(const float4*)&g_v[(size_t)row * NT + threadIdx.x * 4];
    float s = p.x + p.y + p.z + p.w;
    int lane = threadIdx.x & 31, w = threadIdx.x >> 5;
#pragma unroll
    for (int o = 16; o > 0; o >>= 1) s += __shfl_xor_sync(0xffffffffu, s, o);
    if (lane == 0) sbuf[w] = s;
    __syncthreads();
    if (threadIdx.x == 0) {
        float t = 0.f;
        for (int i = 0; i < 8; i++) t += sbuf[i];
        g_vsum[row] = t;
    }
}

// ============ Kernel 5: finalize InstanceNorm params ============
__global__ __launch_bounds__(256) void finalize_kernel(const float* __restrict__ gamma,
                                                       const float* __restrict__ beta) {
    __shared__ float sbuf[8];
    int grp = blockIdx.x;
    float s = 0.f;
    for (int i = threadIdx.x; i < NT; i += 256) s += g_rowsq[grp * NT + i];
    int lane = threadIdx.x & 31, w = threadIdx.x >> 5;
#pragma unroll
    for (int o = 16; o > 0; o >>= 1) s += __shfl_xor_sync(0xffffffffu, s, o);
    if (lane == 0) sbuf[w] = s;
    __syncthreads();
    if (threadIdx.x == 0) {
        float sumsq = 0.f;
        for (int i = 0; i < 8; i++) sumsq += sbuf[i];
        const float invN = 1.f / (1024.f * 1024.f);
        float mean = 1.f / 1024.f;
        float var = sumsq * invN - mean * mean;
        int h = grp & 7;
        float alpha = gamma[h] * rsqrtf(var + EPS_IN);
        g_alpha[grp] = alpha;
        g_betac[grp] = beta[h] - alpha * mean;
    }
}

// ============ Kernel 6: AV (fp16 mma) + folded InstanceNorm ============
// out[q,d] = alpha * sum_T p[q,T] v[d,T] + betac * vsum[d]
__global__ __launch_bounds__(256) void av_fp16() {
    int bh = blockIdx.y;
    int b = bh >> 3, h = bh & 7;
    const __half* P = g_ph + (size_t)bh * NT * NT;                 // [q][T]
    const __half* V = g_vh + (size_t)(b * NC + h * NHD) * NT;      // [d][T]
    float* out = g_out + (size_t)bh * NT * NHD;
    int qBase = blockIdx.x * 128;

    __shared__ uint32_t Ps[128][20];   // half2: [q][T/2]
    __shared__ uint32_t Vs[64][20];    // half2: [d][T/2]

    int tid = threadIdx.x, lane = tid & 31, wid = tid >> 5;
    int wm = wid >> 1, wn = wid & 1;
    int lr = lane >> 2, lk = lane & 3;

    float acc[2][4][4];
#pragma unroll
    for (int mi = 0; mi < 2; mi++)
#pragma unroll
        for (int nj = 0; nj < 4; nj++)
#pragma unroll
            for (int ci = 0; ci < 4; ci++) acc[mi][nj][ci] = 0.f;

    for (int k0 = 0; k0 < NT; k0 += 32) {
#pragma unroll
        for (int pass = 0; pass < 2; pass++) {
            int idx = tid + pass * 256;
            int row = idx >> 2, seg = idx & 3;
            uint4 pv = *(const uint4*)&P[(size_t)(qBase + row) * NT + k0 + seg * 8];
            *(uint4*)&Ps[row][seg * 4] = pv;
        }
        {
            int row = tid >> 2, seg = tid & 3;
            uint4 vv = *(const uint4*)&V[(size_t)row * NT + k0 + seg * 8];
            *(uint4*)&Vs[row][seg * 4] = vv;
        }
        __syncthreads();
#pragma unroll
        for (int ci = 0; ci < 2; ci++) {
            int kc = ci * 8;
            uint32_t af[2][4], bf[4][2];
#pragma unroll
            for (int mi = 0; mi < 2; mi++) {
                int m0 = wm * 32 + mi * 16 + lr;
                af[mi][0] = Ps[m0][kc + lk];
                af[mi][1] = Ps[m0 + 8][kc + lk];
                af[mi][2] = Ps[m0][kc + lk + 4];
                af[mi][3] = Ps[m0 + 8][kc + lk + 4];
            }
#pragma unroll
            for (int nj = 0; nj < 4; nj++) {
                int n0 = wn * 32 + nj * 8 + lr;
                bf[nj][0] = Vs[n0][kc + lk];
                bf[nj][1] = Vs[n0][kc + lk + 4];
            }
#pragma unroll
            for (int mi = 0; mi < 2; mi++)
#pragma unroll
                for (int nj = 0; nj < 4; nj++) mma16h(acc[mi][nj], af[mi], bf[nj]);
        }
        __syncthreads();
    }

    float alpha = g_alpha[bh], bc = g_betac[bh];
#pragma unroll
    for (int mi = 0; mi < 2; mi++) {
        int r = qBase + wm * 32 + mi * 16 + lr;
#pragma unroll
        for (int nj = 0; nj < 4; nj++) {
            int d0 = wn * 32 + nj * 8 + lk * 2;
            float vs0 = g_vsum[bh * NHD + d0], vs1 = g_vsum[bh * NHD + d0 + 1];
            *(float2*)&out[(size_t)r * NHD + d0] =
                make_float2(alpha * acc[mi][nj][0] + bc * vs0,
                            alpha * acc[mi][nj][1] + bc * vs1);
            *(float2*)&out[(size_t)(r + 8) * NHD + d0] =
                make_float2(alpha * acc[mi][nj][2] + bc * vs0,
                            alpha * acc[mi][nj][3] + bc * vs1);
        }
    }
}

// ============ Kernel 7: projection ============
__global__ __launch_bounds__(256) void proj_tf32(const float* __restrict__ w_proj,
                                                 const float* __restrict__ b_proj,
                                                 float* __restrict__ outF) {
    int b = blockIdx.z;
    int coBase = blockIdx.y * 128;
    int tBase = blockIdx.x * 128;
    const float* mid = g_out + (size_t)b * NT * NC;

    __shared__ uint32_t As[128][36];
    __shared__ uint32_t Bs[128][36];

    int tid = threadIdx.x, lane = tid & 31, wid = tid >> 5;
    int wm = wid >> 2, wn = wid & 3;
    int lr = lane >> 2, lk = lane & 3;

    float acc[4][4][4];
#pragma unroll
    for (int mi = 0; mi < 4; mi++)
#pragma unroll
        for (int nj = 0; nj < 4; nj++)
#pragma unroll
            for (int ci = 0; ci < 4; ci++) acc[mi][nj][ci] = 0.f;

    for (int k0 = 0; k0 < NC; k0 += 32) {
#pragma unroll
        for (int i = 0; i < 4; i++) {
            int idx = tid + i * 256;
            int r = idx >> 3, c4 = (idx & 7) * 4;
            float4 w4 = *(const float4*)&w_proj[(size_t)(coBase + r) * NC + k0 + c4];
            *(uint4*)&As[r][c4] = make_uint4(f2tf(w4.x), f2tf(w4.y), f2tf(w4.z), f2tf(w4.w));
            float4 m4 = *(const float4*)&mid[(size_t)(tBase + r) * NC + k0 + c4];
            *(uint4*)&Bs[r][c4] = make_uint4(f2tf(m4.x), f2tf(m4.y), f2tf(m4.z), f2tf(m4.w));
        }
        __syncthreads();
#pragma unroll
        for (int kk = 0; kk < 32; kk += 8) {
            uint32_t af[4][4], bf[4][2];
#pragma unroll
            for (int mi = 0; mi < 4; mi++) {
                int m0 = wm * 64 + mi * 16 + lr;
                af[mi][0] = As[m0][kk + lk];
                af[mi][1] = As[m0 + 8][kk + lk];
                af[mi][2] = As[m0][kk + lk + 4];
                af[mi][3] = As[m0 + 8][kk + lk + 4];
            }
#pragma unroll
            for (int nj = 0; nj < 4; nj++) {
                int n0 = wn * 32 + nj * 8 + lr;
                bf[nj][0] = Bs[n0][kk + lk];
                bf[nj][1] = Bs[n0][kk + lk + 4];
            }
#pragma unroll
            for (int mi = 0; mi < 4; mi++)
#pragma unroll
                for (int nj = 0; nj < 4; nj++) mma8(acc[mi][nj], af[mi], bf[nj]);
        }
        __syncthreads();
    }
#pragma unroll
    for (int mi = 0; mi < 4; mi++) {
        int co = coBase + wm * 64 + mi * 16 + lr;
        float bias0 = b_proj[co], bias1 = b_proj[co + 8];
        float* op0 = outF + (size_t)b * NC * NT + (size_t)co * NT;
        float* op1 = op0 + (size_t)8 * NT;
#pragma unroll
        for (int nj = 0; nj < 4; nj++) {
            int cc = tBase + wn * 32 + nj * 8 + lk * 2;
            *(float2*)&op0[cc] = make_float2(acc[mi][nj][0] + bias0, acc[mi][nj][1] + bias0);
            *(float2*)&op1[cc] = make_float2(acc[mi][nj][2] + bias1, acc[mi][nj][3] + bias1);
        }
    }
}

// ---------------- launch ----------------
extern "C" void kernel_launch(void* const* d_in, const int* in_sizes, int n_in,
                              void* d_out, int out_size) {
    (void)in_sizes; (void)n_in; (void)out_size;
    const float* x        = (const float*)d_in[0];
    const float* w_q      = (const float*)d_in[1];
    const float* w_k      = (const float*)d_in[2];
    const float* w_v      = (const float*)d_in[3];
    const float* w_head   = (const float*)d_in[4];
    const float* in_gamma = (const float*)d_in[5];
    const float* in_beta  = (const float*)d_in[6];
    const float* w_proj   = (const float*)d_in[7];
    const float* b_proj   = (const float*)d_in[8];
    float* outF = (float*)d_out;

    qkv_tf32<<<dim3(8, 4, 12), 256>>>(x, w_q, w_k, w_v);
    qk_tf32<<<dim3(8, 8, 32), 256>>>();
    mixsm_kernel<<<dim3(1024, 4), 256>>>(w_head);
    vsum_kernel<<<2048, 256>>>();
    finalize_kernel<<<32, 256>>>(in_gamma, in_beta);
    av_fp16<<<dim3(8, 32), 256>>>();
    proj_tf32<<<dim3(8, 4, 4), 256>>>(w_proj, b_proj, outF);
}